// round 1
// baseline (speedup 1.0000x reference)
#include <cuda_runtime.h>

#define BB 16
#define CC 128
#define OO 128
#define HH 112
#define WW 112
#define HWSZ (HH*WW)        // 12544
#define KTAPS 3
#define TH 28               // h-rows per pass2 block (112/28 = 4 tiles)

// Scratch: G[k][b][o][h][w]  (3*16*128*12544 floats = 308 MB)
__device__ float g_G[3 * BB * OO * HWSZ];
// Transposed weights: W2[k][c][o]
__device__ float g_W2[3 * CC * OO];

// 8 skeleton directions (dy, dx)
__constant__ int c_dy[8] = {0, 1, 1,  1,  0, -1, -1, -1};
__constant__ int c_dx[8] = {1, 1, 0, -1, -1, -1,  0,  1};

// ---------------------------------------------------------------------------
// Pass 0: transpose weight [O,C,K] -> W2[k][c][o] so pass1 loads coalesce.
// ---------------------------------------------------------------------------
__global__ void transpose_w_kernel(const float* __restrict__ w) {
    int i = blockIdx.x * 256 + threadIdx.x;
    if (i < 3 * CC * OO) {
        int k = i / (CC * OO);
        int r = i % (CC * OO);
        int c = r / OO;
        int o = r % OO;
        g_W2[i] = w[(o * CC + c) * KTAPS + k];
    }
}

// ---------------------------------------------------------------------------
// Pass 1: G[k][b][o][n] = sum_c W2[k][c][o] * x[b][c][n]
// GEMM per (k,b): M=128(o) x N=12544(hw) x K=128(c).
// Block tile 128x128, 256 threads, 8x8 per-thread register tile.
// grid = (98 n-tiles, 3 k, 16 b)
// ---------------------------------------------------------------------------
__global__ __launch_bounds__(256) void pass1_gemm(const float* __restrict__ x) {
    const int n0 = blockIdx.x * 128;
    const int kk = blockIdx.y;
    const int b  = blockIdx.z;

    __shared__ __align__(16) float Ws[32 * 128];  // [c][o]
    __shared__ __align__(16) float Xs[32 * 128];  // [c][n]

    const int tid = threadIdx.x;
    const int tn = tid & 15;   // 16 n-groups
    const int tm = tid >> 4;   // 16 m-groups

    float acc[8][8];
    #pragma unroll
    for (int i = 0; i < 8; i++)
        #pragma unroll
        for (int j = 0; j < 8; j++) acc[i][j] = 0.0f;

    const float* wbase = g_W2 + kk * CC * OO;
    const float* xbase = x + (size_t)(b * CC) * HWSZ + n0;

    for (int c0 = 0; c0 < CC; c0 += 32) {
        // Load W chunk: 32 rows x 128 o = 4096 floats, contiguous.
        const float4* wsrc = (const float4*)(wbase + c0 * OO);
        #pragma unroll
        for (int t = 0; t < 4; t++) {
            int idx = t * 256 + tid;          // 0..1023 float4s
            ((float4*)Ws)[idx] = wsrc[idx];
        }
        // Load X chunk: 32 rows of 128 contiguous pixels.
        #pragma unroll
        for (int t = 0; t < 4; t++) {
            int idx = t * 256 + tid;
            int c = idx >> 5;                 // /32
            int q = idx & 31;
            ((float4*)Xs)[c * 32 + q] =
                ((const float4*)(xbase + (size_t)(c0 + c) * HWSZ))[q];
        }
        __syncthreads();

        #pragma unroll
        for (int ccx = 0; ccx < 32; ccx++) {
            float4 w0 = ((float4*)Ws)[ccx * 32 + tm * 2];
            float4 w1 = ((float4*)Ws)[ccx * 32 + tm * 2 + 1];
            float4 x0 = ((float4*)Xs)[ccx * 32 + tn];        // cols tn*4..+3
            float4 x1 = ((float4*)Xs)[ccx * 32 + 16 + tn];   // cols 64+tn*4..+3
            float wf[8] = {w0.x, w0.y, w0.z, w0.w, w1.x, w1.y, w1.z, w1.w};
            float xf[8] = {x0.x, x0.y, x0.z, x0.w, x1.x, x1.y, x1.z, x1.w};
            #pragma unroll
            for (int i = 0; i < 8; i++)
                #pragma unroll
                for (int j = 0; j < 8; j++)
                    acc[i][j] += wf[i] * xf[j];
        }
        __syncthreads();
    }

    // Store: rows m = tm*8+i, cols split {tn*4, 64+tn*4}.
    float* gb = g_G + ((size_t)(kk * BB + b) * OO) * HWSZ + n0;
    #pragma unroll
    for (int i = 0; i < 8; i++) {
        int m = tm * 8 + i;
        float4 v0 = make_float4(acc[i][0], acc[i][1], acc[i][2], acc[i][3]);
        float4 v1 = make_float4(acc[i][4], acc[i][5], acc[i][6], acc[i][7]);
        *(float4*)(gb + (size_t)m * HWSZ + tn * 4) = v0;
        *(float4*)(gb + (size_t)m * HWSZ + 64 + tn * 4) = v1;
    }
}

// ---------------------------------------------------------------------------
// Pass 2: out[b,o,d,h,w] = G0[h-dy,w-dx] + G1[h,w] + G2[h+dy,w+dx]  (OOB = 0)
// Block handles one (b,o) and TH=28 rows; stages 30 rows of each G_k in smem.
// grid = B*O*4 blocks, 256 threads.
// ---------------------------------------------------------------------------
__global__ __launch_bounds__(256) void pass2_shift(float* __restrict__ out) {
    const int bid = blockIdx.x;
    const int ht = bid & 3;
    const int bo = bid >> 2;        // b*O + o
    const int o  = bo & 127;
    const int b  = bo >> 7;
    const int h0 = ht * TH;

    __shared__ __align__(16) float Gs[3][TH + 2][116];  // padded rows, 16B aligned

    const int tid = threadIdx.x;

    // Load rows h0-1 .. h0+TH of each G_k (zero-fill OOB rows).
    for (int idx = tid; idx < 3 * (TH + 2) * 28; idx += 256) {
        int k   = idx / ((TH + 2) * 28);
        int r   = idx % ((TH + 2) * 28);
        int row = r / 28;
        int q   = r % 28;
        int gh  = h0 - 1 + row;
        float4 v = make_float4(0.f, 0.f, 0.f, 0.f);
        if (gh >= 0 && gh < HH)
            v = *(const float4*)(g_G +
                ((size_t)((k * BB + b) * OO + o)) * HWSZ + gh * WW + q * 4);
        *(float4*)&Gs[k][row][q * 4] = v;
    }
    __syncthreads();

    float* ob = out + ((size_t)(b * OO + o) * 8) * HWSZ;

    // 8 dirs x TH rows x 28 quads; d is slowest so dx/dy are warp-uniform.
    for (int idx = tid; idx < 8 * TH * 28; idx += 256) {
        int d  = idx / (TH * 28);
        int r  = idx % (TH * 28);
        int hl = r / 28;
        int q  = r % 28;
        int dy = c_dy[d];
        int dx = c_dx[d];
        int r0 = hl + 1 - dy;
        int r2 = hl + 1 + dy;

        float4 A = *(float4*)&Gs[1][hl + 1][q * 4];
        float4 Bv = *(float4*)&Gs[0][r0][q * 4];
        float4 Cv = *(float4*)&Gs[2][r2][q * 4];
        float4 res;
        if (dx == 0) {
            res.x = A.x + Bv.x + Cv.x;
            res.y = A.y + Bv.y + Cv.y;
            res.z = A.z + Bv.z + Cv.z;
            res.w = A.w + Bv.w + Cv.w;
        } else if (dx == 1) {
            // t0 at w-1, t2 at w+1
            float bl = (q > 0)  ? Gs[0][r0][q * 4 - 1] : 0.0f;
            float cr = (q < 27) ? Gs[2][r2][q * 4 + 4] : 0.0f;
            res.x = A.x + bl   + Cv.y;
            res.y = A.y + Bv.x + Cv.z;
            res.z = A.z + Bv.y + Cv.w;
            res.w = A.w + Bv.z + cr;
        } else {
            // dx == -1: t0 at w+1, t2 at w-1
            float br = (q < 27) ? Gs[0][r0][q * 4 + 4] : 0.0f;
            float cl = (q > 0)  ? Gs[2][r2][q * 4 - 1] : 0.0f;
            res.x = A.x + Bv.y + cl;
            res.y = A.y + Bv.z + Cv.x;
            res.z = A.z + Bv.w + Cv.y;
            res.w = A.w + br   + Cv.z;
        }
        *(float4*)(ob + (size_t)d * HWSZ + (h0 + hl) * WW + q * 4) = res;
    }
}

// ---------------------------------------------------------------------------
extern "C" void kernel_launch(void* const* d_in, const int* in_sizes, int n_in,
                              void* d_out, int out_size) {
    const float* x = (const float*)d_in[0];       // [16,128,112,112]
    const float* w = (const float*)d_in[1];       // [128,128,3]
    float* out = (float*)d_out;                   // [16,128,8,112,112]

    transpose_w_kernel<<<(3 * CC * OO + 255) / 256, 256>>>(w);

    dim3 g1(HWSZ / 128, 3, BB);                   // (98, 3, 16)
    pass1_gemm<<<g1, 256>>>(x);

    pass2_shift<<<BB * OO * 4, 256>>>(out);
}

// round 2
// speedup vs baseline: 1.0061x; 1.0061x over previous
#include <cuda_runtime.h>

#define BB 16
#define CC 128
#define OO 128
#define HH 112
#define WW 112
#define HWSZ (HH*WW)        // 12544
#define KTAPS 3
#define TH 28               // h-rows per pass2 block (112/28 = 4 tiles)

// Scratch: G[k][b][o][h][w]  (3*16*128*12544 floats = 308 MB)
__device__ __align__(128) float g_G[3 * BB * OO * HWSZ];
// Transposed weights: W2[k][c][o]
__device__ __align__(128) float g_W2[3 * CC * OO];

// 8 skeleton directions (dy, dx)
__constant__ int c_dy[8] = {0, 1, 1,  1,  0, -1, -1, -1};
__constant__ int c_dx[8] = {1, 1, 0, -1, -1, -1,  0,  1};

// ---------------------------------------------------------------------------
// Packed f32x2 helpers (sm_103a)
// ---------------------------------------------------------------------------
__device__ __forceinline__ void fma2(unsigned long long& d,
                                     unsigned long long a,
                                     unsigned long long b) {
    asm("fma.rn.f32x2 %0, %1, %2, %0;" : "+l"(d) : "l"(a), "l"(b));
}
__device__ __forceinline__ unsigned long long dup2(float v) {
    unsigned long long r;
    asm("mov.b64 %0, {%1, %1};" : "=l"(r) : "f"(v));
    return r;
}
__device__ __forceinline__ void cp_async16(unsigned dst, const void* src) {
    asm volatile("cp.async.ca.shared.global [%0], [%1], 16;"
                 :: "r"(dst), "l"(src));
}
#define CP_COMMIT() asm volatile("cp.async.commit_group;" ::: "memory")
#define CP_WAIT0()  asm volatile("cp.async.wait_group 0;" ::: "memory")

// ---------------------------------------------------------------------------
// Pass 0: transpose weight [O,C,K] -> W2[k][c][o] so pass1 loads coalesce.
// ---------------------------------------------------------------------------
__global__ void transpose_w_kernel(const float* __restrict__ w) {
    int i = blockIdx.x * 256 + threadIdx.x;
    if (i < 3 * CC * OO) {
        int k = i / (CC * OO);
        int r = i % (CC * OO);
        int c = r / OO;
        int o = r % OO;
        g_W2[i] = w[(o * CC + c) * KTAPS + k];
    }
}

// ---------------------------------------------------------------------------
// Pass 1 (v2): G[k][b][o][n] = sum_c W2[k][c][o] * x[b][c][n], all 3 k per CTA.
// Xs[128c][128px] resident (64 KB). Ws double-buffered 32c chunks via cp.async.
// 256 threads, 8x8 register tile per thread, packed f32x2 FMA (pairs along n).
// grid = (98 n-tiles, 16 b), 2 CTAs/SM.
// ---------------------------------------------------------------------------
__global__ __launch_bounds__(256, 2) void pass1_gemm(const float* __restrict__ x) {
    const int n0 = blockIdx.x * 128;
    const int b  = blockIdx.y;

    __shared__ __align__(16) float Xs[128][128];      // 64 KB
    __shared__ __align__(16) float Ws[2][32][128];    // 32 KB

    const int tid = threadIdx.x;
    const int tn = tid & 15;   // 16 n-groups
    const int tm = tid >> 4;   // 16 m-groups

    // ---- Load Xs: 128 c-rows x 128 px (read x exactly once per tile) ----
    const float* xbase = x + (size_t)b * CC * HWSZ + n0;
    #pragma unroll
    for (int t = 0; t < 16; t++) {
        int idx = t * 256 + tid;      // 0..4095 float4
        int c = idx >> 5;
        int q = idx & 31;
        *(float4*)&Xs[c][q * 4] = ((const float4*)(xbase + (size_t)c * HWSZ))[q];
    }

    // ---- Prefetch Ws chunk 0 (k=0, c0=0) ----
    {
        const float4* src = (const float4*)g_W2;
        unsigned dst = (unsigned)__cvta_generic_to_shared(&Ws[0][0][0]);
        #pragma unroll
        for (int t = 0; t < 4; t++) {
            int idx = t * 256 + tid;
            cp_async16(dst + idx * 16, src + idx);
        }
        CP_COMMIT();
    }
    CP_WAIT0();
    __syncthreads();

    unsigned long long acc[8][4];

    #pragma unroll 1
    for (int k = 0; k < 3; k++) {
        #pragma unroll
        for (int i = 0; i < 8; i++)
            #pragma unroll
            for (int j = 0; j < 4; j++) acc[i][j] = 0ULL;

        #pragma unroll 1
        for (int ch = 0; ch < 4; ch++) {
            const int ci = k * 4 + ch;
            const int buf = ci & 1;

            // Prefetch next Ws chunk into the other buffer (overlaps compute).
            if (ci < 11) {
                const int cn = ci + 1;
                const float4* src =
                    (const float4*)(g_W2 + (cn >> 2) * CC * OO + (cn & 3) * 32 * OO);
                unsigned dst = (unsigned)__cvta_generic_to_shared(&Ws[cn & 1][0][0]);
                #pragma unroll
                for (int t = 0; t < 4; t++) {
                    int idx = t * 256 + tid;
                    cp_async16(dst + idx * 16, src + idx);
                }
                CP_COMMIT();
            }

            // ---- Compute 32 c-steps from resident smem ----
            #pragma unroll 8
            for (int cc = 0; cc < 32; cc++) {
                const int crow = ch * 32 + cc;
                float4 w0 = *(float4*)&Ws[buf][cc][tm * 8];
                float4 w1 = *(float4*)&Ws[buf][cc][tm * 8 + 4];
                ulonglong2 xa = *(ulonglong2*)&Xs[crow][tn * 4];
                ulonglong2 xb = *(ulonglong2*)&Xs[crow][64 + tn * 4];
                float wf[8] = {w0.x, w0.y, w0.z, w0.w, w1.x, w1.y, w1.z, w1.w};
                #pragma unroll
                for (int i = 0; i < 8; i++) {
                    unsigned long long wp = dup2(wf[i]);
                    fma2(acc[i][0], wp, xa.x);
                    fma2(acc[i][1], wp, xa.y);
                    fma2(acc[i][2], wp, xb.x);
                    fma2(acc[i][3], wp, xb.y);
                }
            }

            CP_WAIT0();
            __syncthreads();
        }

        // ---- Store G[k] tile ----
        float* gk = g_G + ((size_t)(k * BB + b) * OO) * HWSZ + n0;
        #pragma unroll
        for (int i = 0; i < 8; i++) {
            int m = tm * 8 + i;
            ulonglong2 v0, v1;
            v0.x = acc[i][0]; v0.y = acc[i][1];
            v1.x = acc[i][2]; v1.y = acc[i][3];
            *(ulonglong2*)(gk + (size_t)m * HWSZ + tn * 4) = v0;
            *(ulonglong2*)(gk + (size_t)m * HWSZ + 64 + tn * 4) = v1;
        }
    }
}

// ---------------------------------------------------------------------------
// Pass 2: out[b,o,d,h,w] = G0[h-dy,w-dx] + G1[h,w] + G2[h+dy,w+dx]  (OOB = 0)
// Block handles one (b,o) and TH=28 rows; stages 30 rows of each G_k in smem.
// grid = B*O*4 blocks, 256 threads.
// ---------------------------------------------------------------------------
__global__ __launch_bounds__(256) void pass2_shift(float* __restrict__ out) {
    const int bid = blockIdx.x;
    const int ht = bid & 3;
    const int bo = bid >> 2;        // b*O + o
    const int o  = bo & 127;
    const int b  = bo >> 7;
    const int h0 = ht * TH;

    __shared__ __align__(16) float Gs[3][TH + 2][116];

    const int tid = threadIdx.x;

    // Load rows h0-1 .. h0+TH of each G_k (zero-fill OOB rows).
    for (int idx = tid; idx < 3 * (TH + 2) * 28; idx += 256) {
        int k   = idx / ((TH + 2) * 28);
        int r   = idx % ((TH + 2) * 28);
        int row = r / 28;
        int q   = r % 28;
        int gh  = h0 - 1 + row;
        float4 v = make_float4(0.f, 0.f, 0.f, 0.f);
        if (gh >= 0 && gh < HH)
            v = *(const float4*)(g_G +
                ((size_t)((k * BB + b) * OO + o)) * HWSZ + gh * WW + q * 4);
        *(float4*)&Gs[k][row][q * 4] = v;
    }
    __syncthreads();

    float* ob = out + ((size_t)(b * OO + o) * 8) * HWSZ;

    // 8 dirs x TH rows x 28 quads; d is slowest so dx/dy are warp-uniform.
    for (int idx = tid; idx < 8 * TH * 28; idx += 256) {
        int d  = idx / (TH * 28);
        int r  = idx % (TH * 28);
        int hl = r / 28;
        int q  = r % 28;
        int dy = c_dy[d];
        int dx = c_dx[d];
        int r0 = hl + 1 - dy;
        int r2 = hl + 1 + dy;

        float4 A  = *(float4*)&Gs[1][hl + 1][q * 4];
        float4 Bv = *(float4*)&Gs[0][r0][q * 4];
        float4 Cv = *(float4*)&Gs[2][r2][q * 4];
        float4 res;
        if (dx == 0) {
            res.x = A.x + Bv.x + Cv.x;
            res.y = A.y + Bv.y + Cv.y;
            res.z = A.z + Bv.z + Cv.z;
            res.w = A.w + Bv.w + Cv.w;
        } else if (dx == 1) {
            float bl = (q > 0)  ? Gs[0][r0][q * 4 - 1] : 0.0f;
            float cr = (q < 27) ? Gs[2][r2][q * 4 + 4] : 0.0f;
            res.x = A.x + bl   + Cv.y;
            res.y = A.y + Bv.x + Cv.z;
            res.z = A.z + Bv.y + Cv.w;
            res.w = A.w + Bv.z + cr;
        } else {
            float br = (q < 27) ? Gs[0][r0][q * 4 + 4] : 0.0f;
            float cl = (q > 0)  ? Gs[2][r2][q * 4 - 1] : 0.0f;
            res.x = A.x + Bv.y + cl;
            res.y = A.y + Bv.z + Cv.x;
            res.z = A.z + Bv.w + Cv.y;
            res.w = A.w + br   + Cv.z;
        }
        *(float4*)(ob + (size_t)d * HWSZ + (h0 + hl) * WW + q * 4) = res;
    }
}

// ---------------------------------------------------------------------------
extern "C" void kernel_launch(void* const* d_in, const int* in_sizes, int n_in,
                              void* d_out, int out_size) {
    const float* x = (const float*)d_in[0];       // [16,128,112,112]
    const float* w = (const float*)d_in[1];       // [128,128,3]
    float* out = (float*)d_out;                   // [16,128,8,112,112]

    transpose_w_kernel<<<(3 * CC * OO + 255) / 256, 256>>>(w);

    dim3 g1(HWSZ / 128, BB);                      // (98, 16)
    pass1_gemm<<<g1, 256>>>(x);

    pass2_shift<<<BB * OO * 4, 256>>>(out);
}

// round 5
// speedup vs baseline: 1.3712x; 1.3629x over previous
#include <cuda_runtime.h>
#include <cuda_bf16.h>
#include <cstdint>

#define BB 16
#define CC 128
#define OO 128
#define HH 112
#define WW 112
#define HWSZ (HH*WW)        // 12544
#define TH 28

#define XPITCH 136          // padded row (elems) -> 272 B, conflict-free ldmatrix
#define WTAP_BYTES (2 * 128 * XPITCH * 2)   // hi+lo per tap = 69632 B
#define SPLIT_BYTES (128 * XPITCH * 2)      // 34816 B

// Scratch: G[k][b][o][h][w]  (3*16*128*12544 floats = 308 MB)
__device__ __align__(128) float g_G[3 * BB * OO * HWSZ];
// Prepacked bf16 weights: [tap][hi|lo][o=128][XPITCH] (pad cols zeroed)
__device__ __align__(128) unsigned short g_Wt[3 * 2 * 128 * XPITCH];

__constant__ int c_dy[8] = {0, 1, 1,  1,  0, -1, -1, -1};
__constant__ int c_dx[8] = {1, 1, 0, -1, -1, -1,  0,  1};

// ---------------------------------------------------------------------------
// Helpers
// ---------------------------------------------------------------------------
__device__ __forceinline__ uint32_t smem_u32(const void* p) {
    uint32_t a;
    asm("{ .reg .u64 t; cvta.to.shared.u64 t, %1; cvt.u32.u64 %0, t; }" : "=r"(a) : "l"(p));
    return a;
}
__device__ __forceinline__ void cp_async16(uint32_t dst, const void* src) {
    asm volatile("cp.async.ca.shared.global [%0], [%1], 16;" :: "r"(dst), "l"(src));
}
#define CP_COMMIT() asm volatile("cp.async.commit_group;" ::: "memory")
#define CP_WAIT0()  asm volatile("cp.async.wait_group 0;" ::: "memory")

__device__ __forceinline__ void ldmat_x4(uint32_t* r, uint32_t addr) {
    asm volatile("ldmatrix.sync.aligned.m8n8.x4.shared.b16 {%0,%1,%2,%3}, [%4];"
                 : "=r"(r[0]), "=r"(r[1]), "=r"(r[2]), "=r"(r[3]) : "r"(addr));
}
__device__ __forceinline__ void ldmat_x4_t(uint32_t* r, uint32_t addr) {
    asm volatile("ldmatrix.sync.aligned.m8n8.x4.trans.shared.b16 {%0,%1,%2,%3}, [%4];"
                 : "=r"(r[0]), "=r"(r[1]), "=r"(r[2]), "=r"(r[3]) : "r"(addr));
}
__device__ __forceinline__ void mma16816(float* d, const uint32_t* a,
                                         uint32_t b0, uint32_t b1) {
    asm volatile("mma.sync.aligned.m16n8k16.row.col.f32.bf16.bf16.f32 "
                 "{%0,%1,%2,%3}, {%4,%5,%6,%7}, {%8,%9}, {%0,%1,%2,%3};"
                 : "+f"(d[0]), "+f"(d[1]), "+f"(d[2]), "+f"(d[3])
                 : "r"(a[0]), "r"(a[1]), "r"(a[2]), "r"(a[3]), "r"(b0), "r"(b1));
}

// ---------------------------------------------------------------------------
// Weight prep: split w[o][c][k] -> bf16 hi/lo, layout [tap][split][o][XPITCH].
// ---------------------------------------------------------------------------
__global__ void prep_w_kernel(const float* __restrict__ w) {
    int i = blockIdx.x * 256 + threadIdx.x;
    if (i >= 3 * 128 * XPITCH) return;
    int k = i / (128 * XPITCH);
    int r = i % (128 * XPITCH);
    int o = r / XPITCH;
    int c = r % XPITCH;
    unsigned short hv = 0, lv = 0;
    if (c < 128) {
        float v = w[(o * 128 + c) * 3 + k];
        __nv_bfloat16 h = __float2bfloat16(v);
        __nv_bfloat16 l = __float2bfloat16(v - __bfloat162float(h));
        hv = __bfloat16_as_ushort(h);
        lv = __bfloat16_as_ushort(l);
    }
    int base = k * 2 * 128 * XPITCH;
    g_Wt[base + o * XPITCH + c] = hv;
    g_Wt[base + 128 * XPITCH + o * XPITCH + c] = lv;
}

// ---------------------------------------------------------------------------
// Pass 1: G[k][b][o][n] = sum_c W_k[o][c] * x[b][c][n]  via bf16 mma.sync,
// 2-way hi/lo split (3 products). CTA: 128o x 128px, loops 3 taps.
// 256 threads = 8 warps (4m x 2n); warp tile 32o x 64px.
// Dyn smem: Xs hi/lo [c=128][XPITCH] + W double buffer (2 taps x hi/lo).
// ---------------------------------------------------------------------------
__global__ __launch_bounds__(256, 1) void pass1_mma(const float* __restrict__ x) {
    extern __shared__ __align__(16) char dsm[];
    char* xs  = dsm;                         // 2 * 34816
    char* wsb = dsm + 2 * SPLIT_BYTES;       // 2 * 69632

    const int tid = threadIdx.x;
    const int wrp = tid >> 5;
    const int lid = tid & 31;
    const int gid = lid >> 2;   // group id (row within fragment)
    const int tig = lid & 3;    // thread in group
    const int n0 = blockIdx.x * 128;
    const int b  = blockIdx.y;

    const uint32_t xs_u = smem_u32(xs);
    const uint32_t ws_u = smem_u32(wsb);

    // ---- Prefetch W tap0 (hi+lo) into buffer 0 ----
    {
        const char* src = (const char*)g_Wt;
        #pragma unroll
        for (int t = 0; t < 17; t++) {
            int i = t * 256 + tid;
            cp_async16(ws_u + i * 16, src + (size_t)i * 16);
        }
        CP_COMMIT();
    }

    // ---- Load X fp32 (all 128 c-rows), split hi/lo bf16, store [c][px] ----
    const float* xb = x + (size_t)b * CC * HWSZ + n0;
    #pragma unroll
    for (int it = 0; it < 16; it++) {
        int c = it * 8 + wrp;        // warp handles one c-row per iter (0..127)
        int q = lid;                 // float4 index within row
        float4 v = *(const float4*)(xb + (size_t)c * HWSZ + q * 4);
        __nv_bfloat16 h0 = __float2bfloat16(v.x);
        __nv_bfloat16 h1 = __float2bfloat16(v.y);
        __nv_bfloat16 h2 = __float2bfloat16(v.z);
        __nv_bfloat16 h3 = __float2bfloat16(v.w);
        __nv_bfloat16 l0 = __float2bfloat16(v.x - __bfloat162float(h0));
        __nv_bfloat16 l1 = __float2bfloat16(v.y - __bfloat162float(h1));
        __nv_bfloat16 l2 = __float2bfloat16(v.z - __bfloat162float(h2));
        __nv_bfloat16 l3 = __float2bfloat16(v.w - __bfloat162float(h3));
        uint32_t hA = (uint32_t)__bfloat16_as_ushort(h0) | ((uint32_t)__bfloat16_as_ushort(h1) << 16);
        uint32_t hB = (uint32_t)__bfloat16_as_ushort(h2) | ((uint32_t)__bfloat16_as_ushort(h3) << 16);
        uint32_t lA = (uint32_t)__bfloat16_as_ushort(l0) | ((uint32_t)__bfloat16_as_ushort(l1) << 16);
        uint32_t lB = (uint32_t)__bfloat16_as_ushort(l2) | ((uint32_t)__bfloat16_as_ushort(l3) << 16);
        *(uint2*)(xs + c * (XPITCH * 2) + q * 8)               = make_uint2(hA, hB);
        *(uint2*)(xs + SPLIT_BYTES + c * (XPITCH * 2) + q * 8) = make_uint2(lA, lB);
    }

    CP_WAIT0();
    __syncthreads();

    // ---- Warp tiling ----
    const int m0  = (wrp & 3) * 32;     // o offset
    const int n0w = (wrp >> 2) * 64;    // px offset within tile

    // ldmatrix lane address components
    const int mi = lid >> 3;            // matrix index 0..3
    const int mr = lid & 7;             // row within matrix
    const int a_row = (mi & 1) * 8 + mr;       // o sub-row
    const int a_col = (mi >> 1) * 8;           // c sub-col
    const int b_row = (mi & 1) * 8 + mr;       // c (k) sub-row
    const int b_col = (mi >> 1) * 8;           // px sub-col

    float acc[2][8][4];

    #pragma unroll 1
    for (int k = 0; k < 3; k++) {
        // Prefetch next tap into other buffer (overlaps MMA + epilogue).
        if (k < 2) {
            uint32_t dstb = ws_u + ((k + 1) & 1) * WTAP_BYTES;
            const char* src = (const char*)g_Wt + (size_t)(k + 1) * WTAP_BYTES;
            #pragma unroll
            for (int t = 0; t < 17; t++) {
                int i = t * 256 + tid;
                cp_async16(dstb + i * 16, src + (size_t)i * 16);
            }
            CP_COMMIT();
        }

        #pragma unroll
        for (int i = 0; i < 2; i++)
            #pragma unroll
            for (int j = 0; j < 8; j++)
                #pragma unroll
                for (int q = 0; q < 4; q++) acc[i][j][q] = 0.0f;

        const uint32_t wb = ws_u + (k & 1) * WTAP_BYTES;

        #pragma unroll
        for (int ks = 0; ks < 8; ks++) {
            uint32_t ah[2][4], al[2][4];
            #pragma unroll
            for (int mt = 0; mt < 2; mt++) {
                uint32_t ra = wb + (m0 + mt * 16 + a_row) * (XPITCH * 2)
                            + (ks * 16 + a_col) * 2;
                ldmat_x4(ah[mt], ra);
                ldmat_x4(al[mt], ra + SPLIT_BYTES);
            }
            #pragma unroll
            for (int nt2 = 0; nt2 < 4; nt2++) {
                uint32_t bh[4], bl[4];
                uint32_t rb = xs_u + (ks * 16 + b_row) * (XPITCH * 2)
                            + (n0w + nt2 * 16 + b_col) * 2;
                ldmat_x4_t(bh, rb);
                ldmat_x4_t(bl, rb + SPLIT_BYTES);
                #pragma unroll
                for (int mt = 0; mt < 2; mt++) {
                    #pragma unroll
                    for (int j = 0; j < 2; j++) {
                        float* d = acc[mt][nt2 * 2 + j];
                        mma16816(d, ah[mt], bh[j * 2], bh[j * 2 + 1]);  // hi*hi
                        mma16816(d, ah[mt], bl[j * 2], bl[j * 2 + 1]);  // hi*lo
                        mma16816(d, al[mt], bh[j * 2], bh[j * 2 + 1]);  // lo*hi
                    }
                }
            }
        }

        // ---- Epilogue: store G[k] tile ----
        float* gk = g_G + ((size_t)(k * BB + b) * OO) * HWSZ + n0;
        #pragma unroll
        for (int mt = 0; mt < 2; mt++) {
            #pragma unroll
            for (int nt = 0; nt < 8; nt++) {
                int orow = m0 + mt * 16 + gid;
                int col  = n0w + nt * 8 + tig * 2;
                float* p0 = gk + (size_t)orow * HWSZ + col;
                *(float2*)p0 = make_float2(acc[mt][nt][0], acc[mt][nt][1]);
                *(float2*)(p0 + 8 * HWSZ) = make_float2(acc[mt][nt][2], acc[mt][nt][3]);
            }
        }

        if (k < 2) {
            CP_WAIT0();
            __syncthreads();
        }
    }
}

// ---------------------------------------------------------------------------
// Pass 2: out[b,o,d,h,w] = G0[h-dy,w-dx] + G1[h,w] + G2[h+dy,w+dx]  (OOB = 0)
// ---------------------------------------------------------------------------
__global__ __launch_bounds__(256) void pass2_shift(float* __restrict__ out) {
    const int bid = blockIdx.x;
    const int ht = bid & 3;
    const int bo = bid >> 2;
    const int o  = bo & 127;
    const int b  = bo >> 7;
    const int h0 = ht * TH;

    __shared__ __align__(16) float Gs[3][TH + 2][116];

    const int tid = threadIdx.x;

    for (int idx = tid; idx < 3 * (TH + 2) * 28; idx += 256) {
        int k   = idx / ((TH + 2) * 28);
        int r   = idx % ((TH + 2) * 28);
        int row = r / 28;
        int q   = r % 28;
        int gh  = h0 - 1 + row;
        float4 v = make_float4(0.f, 0.f, 0.f, 0.f);
        if (gh >= 0 && gh < HH)
            v = *(const float4*)(g_G +
                ((size_t)((k * BB + b) * OO + o)) * HWSZ + gh * WW + q * 4);
        *(float4*)&Gs[k][row][q * 4] = v;
    }
    __syncthreads();

    float* ob = out + ((size_t)(b * OO + o) * 8) * HWSZ;

    for (int idx = tid; idx < 8 * TH * 28; idx += 256) {
        int d  = idx / (TH * 28);
        int r  = idx % (TH * 28);
        int hl = r / 28;
        int q  = r % 28;
        int dy = c_dy[d];
        int dx = c_dx[d];
        int r0 = hl + 1 - dy;
        int r2 = hl + 1 + dy;

        float4 A  = *(float4*)&Gs[1][hl + 1][q * 4];
        float4 Bv = *(float4*)&Gs[0][r0][q * 4];
        float4 Cv = *(float4*)&Gs[2][r2][q * 4];
        float4 res;
        if (dx == 0) {
            res.x = A.x + Bv.x + Cv.x;
            res.y = A.y + Bv.y + Cv.y;
            res.z = A.z + Bv.z + Cv.z;
            res.w = A.w + Bv.w + Cv.w;
        } else if (dx == 1) {
            float bl = (q > 0)  ? Gs[0][r0][q * 4 - 1] : 0.0f;
            float cr = (q < 27) ? Gs[2][r2][q * 4 + 4] : 0.0f;
            res.x = A.x + bl   + Cv.y;
            res.y = A.y + Bv.x + Cv.z;
            res.z = A.z + Bv.y + Cv.w;
            res.w = A.w + Bv.z + cr;
        } else {
            float br = (q < 27) ? Gs[0][r0][q * 4 + 4] : 0.0f;
            float cl = (q > 0)  ? Gs[2][r2][q * 4 - 1] : 0.0f;
            res.x = A.x + Bv.y + cl;
            res.y = A.y + Bv.z + Cv.x;
            res.z = A.z + Bv.w + Cv.y;
            res.w = A.w + br   + Cv.z;
        }
        *(float4*)(ob + (size_t)d * HWSZ + (h0 + hl) * WW + q * 4) = res;
    }
}

// ---------------------------------------------------------------------------
extern "C" void kernel_launch(void* const* d_in, const int* in_sizes, int n_in,
                              void* d_out, int out_size) {
    const float* x = (const float*)d_in[0];       // [16,128,112,112]
    const float* w = (const float*)d_in[1];       // [128,128,3]
    float* out = (float*)d_out;                   // [16,128,8,112,112]

    prep_w_kernel<<<(3 * 128 * XPITCH + 255) / 256, 256>>>(w);

    const int dyn_smem = 2 * SPLIT_BYTES + 2 * WTAP_BYTES;   // 208896 B
    cudaFuncSetAttribute(pass1_mma,
                         cudaFuncAttributeMaxDynamicSharedMemorySize, dyn_smem);
    dim3 g1(HWSZ / 128, BB);                      // (98, 16)
    pass1_mma<<<g1, 256, dyn_smem>>>(x);

    pass2_shift<<<BB * OO * 4, 256>>>(out);
}